// round 10
// baseline (speedup 1.0000x reference)
#include <cuda_runtime.h>
#include <cstdint>

#define F_EPS 1e-10f

// ---------------------------------------------------------------------------
// Uniform (batch-invariant) constants, pre-differenced to minimize live regs.
// ---------------------------------------------------------------------------
struct Consts {
    float dmu0, dmu1, b0, b1;   // em_j = p*dmu_j + b_j ; b_j = mu2_j - r
    float dSa, dSb, dSc;        // Sigma1 - Sigma2 entries
    float S2a, S2b, S2c;        // Sigma2 entries (+EPS on diag)
    float phi00, phi01, phi10, phi11;
    float s00, s01, s11;        // spd_core = tril @ tril^T
    float omega, lamh;          // lamh = 0.5 * Lambda
};

__device__ __forceinline__ float decode_scalar_bits(int bits) {
    if (bits == 0) return 0.0f;
    float fv = __int_as_float(bits);
    float af = fabsf(fv);
    if (af >= 1e-30f && af <= 1e30f) return fv;   // looks like a float
    return (float)bits;                            // it was an int
}

__device__ __forceinline__ Consts build_consts(const float* __restrict__ omega,
                                               const float* __restrict__ mu1,
                                               const float* __restrict__ mu2,
                                               const float* __restrict__ Sig1,
                                               const float* __restrict__ Sig2,
                                               const float* __restrict__ phi,
                                               const float* __restrict__ ctril,
                                               const int* __restrict__ Lambda,
                                               const int* __restrict__ r) {
    Consts c;
    float4 s1 = __ldg((const float4*)Sig1);
    float4 s2 = __ldg((const float4*)Sig2);
    float4 ph = __ldg((const float4*)phi);
    float4 ctv = __ldg((const float4*)ctril);
    float2 m1 = __ldg((const float2*)mu1);
    float2 m2 = __ldg((const float2*)mu2);

    float rr = decode_scalar_bits(__ldg(r));
    c.dmu0 = m1.x - m2.x;  c.dmu1 = m1.y - m2.y;
    c.b0   = m2.x - rr;    c.b1   = m2.y - rr;
    c.dSa = s1.x - s2.x;   c.dSb = s1.y - s2.y;   c.dSc = s1.w - s2.w;
    c.S2a = s2.x + F_EPS;  c.S2b = s2.y;          c.S2c = s2.w + F_EPS;
    c.phi00 = ph.x; c.phi01 = ph.y;
    c.phi10 = ph.z; c.phi11 = ph.w;
    float C00 = ctv.x, C10 = ctv.z, C11 = ctv.w;
    float e0 = expf(C00), e1 = expf(C11);
    c.s00 = e0 * e0;
    c.s01 = e0 * C10;
    c.s11 = C10 * C10 + e1 * e1;
    c.omega = __ldg(omega);
    c.lamh = 0.5f * decode_scalar_bits(__ldg(Lambda));
    return c;
}

__device__ __forceinline__ void compute_elem(const Consts& c,
                                             float xv, float pv, float dv, float fv,
                                             float& m0, float& m1, float4& cov) {
    float pm1 = 1.0f - pv;
    float em0 = fmaf(pv, c.dmu0, c.b0);
    float em1 = fmaf(pv, c.dmu1, c.b1);

    float a = fmaf(pv, c.dSa, c.S2a);
    float b = fmaf(pv, c.dSb, c.S2b);
    float d = fmaf(pv, c.dSc, c.S2c);

    float inv_l11 = rsqrtf(a);
    float l21     = b * inv_l11;
    float t       = d - l21 * l21;
    float inv_l22 = rsqrtf(t);

    float adj = pv * fmaf(-dv, pm1, 1.0f);
    float s0 = fmaf(c.phi00, adj, c.phi01) * em0;
    float s1 = fmaf(c.phi10, adj, c.phi11) * em1;

    float sti1 = s1 * inv_l22;
    float sti0 = (s0 - l21 * sti1) * inv_l11;

    float mx = c.omega - xv;
    m0 = mx * sti0;
    m1 = mx * sti1;

    float u00 = inv_l11;
    float u11 = inv_l22;
    float u01 = -l21 * inv_l11 * inv_l22;

    float M00 = u00 * u00 * c.s00 + 2.0f * u00 * u01 * c.s01 + u01 * u01 * c.s11;
    float M01 = u11 * fmaf(u00, c.s01, u01 * c.s11);
    float M11 = u11 * u11 * c.s11;

    float sc = c.lamh * fv;
    cov.x = fmaf(sc, M00, F_EPS);
    cov.y = sc * M01;
    cov.z = sc * M01;
    cov.w = fmaf(sc, M11, F_EPS);
}

// ---------------------------------------------------------------------------
// Bulk-async helpers
// ---------------------------------------------------------------------------
__device__ __forceinline__ uint32_t s2u(const void* p) {
    return (uint32_t)__cvta_generic_to_shared(p);
}

__device__ __forceinline__ void mbar_init(uint32_t mb, uint32_t count) {
    asm volatile("mbarrier.init.shared.b64 [%0], %1;" :: "r"(mb), "r"(count) : "memory");
}

__device__ __forceinline__ void mbar_wait(uint32_t mb, uint32_t phase) {
    uint32_t done;
    asm volatile(
        "{\n\t.reg .pred p;\n\t"
        "mbarrier.try_wait.parity.acquire.cta.shared::cta.b64 p, [%1], %2;\n\t"
        "selp.b32 %0, 1, 0, p;\n\t}"
        : "=r"(done) : "r"(mb), "r"(phase) : "memory");
    while (!done) {
        asm volatile(
            "{\n\t.reg .pred p;\n\t"
            "mbarrier.try_wait.parity.acquire.cta.shared::cta.b64 p, [%1], %2, 0x989680;\n\t"
            "selp.b32 %0, 1, 0, p;\n\t}"
            : "=r"(done) : "r"(mb), "r"(phase) : "memory");
    }
}

__device__ __forceinline__ void bulk_g2s(uint32_t smem_dst, const void* gmem_src,
                                         uint32_t bytes, uint32_t mb) {
    asm volatile(
        "cp.async.bulk.shared::cta.global.mbarrier::complete_tx::bytes [%0], [%1], %2, [%3];"
        :: "r"(smem_dst), "l"(gmem_src), "r"(bytes), "r"(mb) : "memory");
}

#define THREADS   256
#define CHUNK     1024
#define STAGES    4                       // 3 chunks in flight + 1 consumed
#define MAX_CTAS  (148 * 3)               // 3 CTAs/SM (64KB smem each)
#define STAGE_F   (4 * CHUNK)             // floats per stage (4 arrays)
#define SMEM_BYTES (STAGES * STAGE_F * 4) // 64 KB dynamic

extern __shared__ float dsm[];            // [STAGES][4][CHUNK]

__global__ void __launch_bounds__(THREADS)
poemv_kernel(const float* __restrict__ x, const float* __restrict__ p,
             const float* __restrict__ dlnf, const float* __restrict__ f,
             float* __restrict__ out_mean, float* __restrict__ out_cov, int B,
             const float* __restrict__ omega, const float* __restrict__ mu1,
             const float* __restrict__ mu2, const float* __restrict__ S1,
             const float* __restrict__ S2, const float* __restrict__ phi,
             const float* __restrict__ ct, const int* __restrict__ Lam,
             const int* __restrict__ rr) {
    __shared__ alignas(8) unsigned long long s_mbar[STAGES];

    const int tid = threadIdx.x;
    const int g = gridDim.x;
    const int nch = (B + CHUNK - 1) / CHUNK;

    if (tid == 0) {
        #pragma unroll
        for (int s = 0; s < STAGES; s++) mbar_init(s2u(&s_mbar[s]), 1);
        asm volatile("fence.proxy.async.shared::cta;" ::: "memory");
    }
    __syncthreads();

    // Prologue: issue up to STAGES-1 full chunks.
    if (tid == 0) {
        #pragma unroll
        for (int st = 0; st < STAGES - 1; st++) {
            int k = blockIdx.x + st * g;
            int base = k * CHUNK;
            if (k < nch && base + CHUNK <= B) {
                float* sb = dsm + st * STAGE_F;
                uint32_t mb = s2u(&s_mbar[st]);
                asm volatile("mbarrier.arrive.expect_tx.shared.b64 _, [%0], %1;"
                             :: "r"(mb), "r"((uint32_t)(CHUNK * 16)) : "memory");
                bulk_g2s(s2u(sb + 0 * CHUNK), x + base,    CHUNK * 4, mb);
                bulk_g2s(s2u(sb + 1 * CHUNK), p + base,    CHUNK * 4, mb);
                bulk_g2s(s2u(sb + 2 * CHUNK), dlnf + base, CHUNK * 4, mb);
                bulk_g2s(s2u(sb + 3 * CHUNK), f + base,    CHUNK * 4, mb);
            }
        }
    }

    const Consts c = build_consts(omega, mu1, mu2, S1, S2, phi, ct, Lam, rr);

    uint32_t phases = 0;     // one parity bit per slot
    int it = 0;
    for (int k = blockIdx.x; k < nch; k += g, ++it) {
        const int slot = it & (STAGES - 1);

        // Refill the slot consumed at iteration it-1 with chunk k+3g.
        if (tid == 0) {
            int kn = k + (STAGES - 1) * g;
            int nbase = kn * CHUNK;
            if (kn < nch && nbase + CHUNK <= B) {
                asm volatile("fence.proxy.async.shared::cta;" ::: "memory");
                const int ns = (it + STAGES - 1) & (STAGES - 1);
                float* sb = dsm + ns * STAGE_F;
                uint32_t mb = s2u(&s_mbar[ns]);
                asm volatile("mbarrier.arrive.expect_tx.shared.b64 _, [%0], %1;"
                             :: "r"(mb), "r"((uint32_t)(CHUNK * 16)) : "memory");
                bulk_g2s(s2u(sb + 0 * CHUNK), x + nbase,    CHUNK * 4, mb);
                bulk_g2s(s2u(sb + 1 * CHUNK), p + nbase,    CHUNK * 4, mb);
                bulk_g2s(s2u(sb + 2 * CHUNK), dlnf + nbase, CHUNK * 4, mb);
                bulk_g2s(s2u(sb + 3 * CHUNK), f + nbase,    CHUNK * 4, mb);
            }
        }

        const int base = k * CHUNK;
        const bool full = (base + CHUNK <= B);

        if (full) {
            mbar_wait(s2u(&s_mbar[slot]), (phases >> slot) & 1u);
            phases ^= 1u << slot;

            const float* sb = dsm + slot * STAGE_F;
            const int s = tid * 4;
            const int i0 = base + s;
            float4 xv = *(const float4*)(sb + 0 * CHUNK + s);
            float4 pv = *(const float4*)(sb + 1 * CHUNK + s);
            float4 dv = *(const float4*)(sb + 2 * CHUNK + s);
            float4 fv = *(const float4*)(sb + 3 * CHUNK + s);

            float m[8];
            float4 cv[4];
            compute_elem(c, xv.x, pv.x, dv.x, fv.x, m[0], m[1], cv[0]);
            compute_elem(c, xv.y, pv.y, dv.y, fv.y, m[2], m[3], cv[1]);
            compute_elem(c, xv.z, pv.z, dv.z, fv.z, m[4], m[5], cv[2]);
            compute_elem(c, xv.w, pv.w, dv.w, fv.w, m[6], m[7], cv[3]);

            *(float4*)(out_mean + (size_t)2 * i0)     = make_float4(m[0], m[1], m[2], m[3]);
            *(float4*)(out_mean + (size_t)2 * i0 + 4) = make_float4(m[4], m[5], m[6], m[7]);
            float4* cb = (float4*)(out_cov + (size_t)4 * i0);
            cb[0] = cv[0]; cb[1] = cv[1]; cb[2] = cv[2]; cb[3] = cv[3];
        } else {
            // partial tail chunk: direct guarded global loads
            for (int kk = 0; kk < 4; kk++) {
                int i = base + tid * 4 + kk;
                if (i < B) {
                    float m0, m1; float4 cvv;
                    compute_elem(c, x[i], p[i], dlnf[i], f[i], m0, m1, cvv);
                    out_mean[(size_t)2 * i]     = m0;
                    out_mean[(size_t)2 * i + 1] = m1;
                    float* cb = out_cov + (size_t)4 * i;
                    cb[0] = cvv.x; cb[1] = cvv.y; cb[2] = cvv.z; cb[3] = cvv.w;
                }
            }
        }
        __syncthreads();   // all readers done before this slot is refilled
    }
}

extern "C" void kernel_launch(void* const* d_in, const int* in_sizes, int n_in,
                              void* d_out, int out_size) {
    const float* x     = (const float*)d_in[0];
    const float* omega = (const float*)d_in[1];
    const float* p     = (const float*)d_in[2];
    const float* dlnf  = (const float*)d_in[3];
    const float* f     = (const float*)d_in[4];
    const float* mu1   = (const float*)d_in[5];
    const float* mu2   = (const float*)d_in[6];
    const float* S1    = (const float*)d_in[7];
    const float* S2    = (const float*)d_in[8];
    const float* phi   = (const float*)d_in[9];
    const float* ct    = (const float*)d_in[10];
    const int*   Lam   = (const int*)d_in[11];
    const int*   r     = (const int*)d_in[12];

    int B = in_sizes[0];
    float* out      = (float*)d_out;
    float* out_mean = out;                       // (B, 2) flattened
    float* out_cov  = out + (size_t)B * 2;       // (B, 2, 2) flattened

    // Raise dynamic smem limit (attribute persists per-function; no alloc).
    cudaFuncSetAttribute(poemv_kernel,
                         cudaFuncAttributeMaxDynamicSharedMemorySize, SMEM_BYTES);

    int chunks = (B + CHUNK - 1) / CHUNK;
    int grid = chunks < MAX_CTAS ? chunks : MAX_CTAS;
    poemv_kernel<<<grid, THREADS, SMEM_BYTES>>>(x, p, dlnf, f, out_mean, out_cov, B,
                                                omega, mu1, mu2, S1, S2, phi, ct, Lam, r);
}

// round 11
// speedup vs baseline: 1.1846x; 1.1846x over previous
#include <cuda_runtime.h>
#include <cstdint>

#define F_EPS 1e-10f

// ---------------------------------------------------------------------------
// Uniform (batch-invariant) constants, pre-differenced to minimize live regs.
// ---------------------------------------------------------------------------
struct Consts {
    float dmu0, dmu1, b0, b1;   // em_j = p*dmu_j + b_j ; b_j = mu2_j - r
    float dSa, dSb, dSc;        // Sigma1 - Sigma2 entries
    float S2a, S2b, S2c;        // Sigma2 entries (+EPS on diag)
    float phi00, phi01, phi10, phi11;
    float s00, s01, s11;        // spd_core = tril @ tril^T
    float omega, lamh;          // lamh = 0.5 * Lambda
};

__device__ __forceinline__ float decode_scalar_bits(int bits) {
    if (bits == 0) return 0.0f;
    float fv = __int_as_float(bits);
    float af = fabsf(fv);
    if (af >= 1e-30f && af <= 1e30f) return fv;   // looks like a float
    return (float)bits;                            // it was an int
}

__device__ __forceinline__ Consts build_consts(const float* __restrict__ omega,
                                               const float* __restrict__ mu1,
                                               const float* __restrict__ mu2,
                                               const float* __restrict__ Sig1,
                                               const float* __restrict__ Sig2,
                                               const float* __restrict__ phi,
                                               const float* __restrict__ ctril,
                                               const int* __restrict__ Lambda,
                                               const int* __restrict__ r) {
    Consts c;
    float4 s1 = __ldg((const float4*)Sig1);
    float4 s2 = __ldg((const float4*)Sig2);
    float4 ph = __ldg((const float4*)phi);
    float4 ctv = __ldg((const float4*)ctril);
    float2 m1 = __ldg((const float2*)mu1);
    float2 m2 = __ldg((const float2*)mu2);

    float rr = decode_scalar_bits(__ldg(r));
    c.dmu0 = m1.x - m2.x;  c.dmu1 = m1.y - m2.y;
    c.b0   = m2.x - rr;    c.b1   = m2.y - rr;
    c.dSa = s1.x - s2.x;   c.dSb = s1.y - s2.y;   c.dSc = s1.w - s2.w;
    c.S2a = s2.x + F_EPS;  c.S2b = s2.y;          c.S2c = s2.w + F_EPS;
    c.phi00 = ph.x; c.phi01 = ph.y;
    c.phi10 = ph.z; c.phi11 = ph.w;
    float C00 = ctv.x, C10 = ctv.z, C11 = ctv.w;
    float e0 = expf(C00), e1 = expf(C11);
    c.s00 = e0 * e0;
    c.s01 = e0 * C10;
    c.s11 = C10 * C10 + e1 * e1;
    c.omega = __ldg(omega);
    c.lamh = 0.5f * decode_scalar_bits(__ldg(Lambda));
    return c;
}

__device__ __forceinline__ void compute_elem(const Consts& c,
                                             float xv, float pv, float dv, float fv,
                                             float& m0, float& m1, float4& cov) {
    float pm1 = 1.0f - pv;
    float em0 = fmaf(pv, c.dmu0, c.b0);
    float em1 = fmaf(pv, c.dmu1, c.b1);

    float a = fmaf(pv, c.dSa, c.S2a);
    float b = fmaf(pv, c.dSb, c.S2b);
    float d = fmaf(pv, c.dSc, c.S2c);

    float inv_l11 = rsqrtf(a);
    float l21     = b * inv_l11;
    float t       = d - l21 * l21;
    float inv_l22 = rsqrtf(t);

    float adj = pv * fmaf(-dv, pm1, 1.0f);
    float s0 = fmaf(c.phi00, adj, c.phi01) * em0;
    float s1 = fmaf(c.phi10, adj, c.phi11) * em1;

    float sti1 = s1 * inv_l22;
    float sti0 = (s0 - l21 * sti1) * inv_l11;

    float mx = c.omega - xv;
    m0 = mx * sti0;
    m1 = mx * sti1;

    float u00 = inv_l11;
    float u11 = inv_l22;
    float u01 = -l21 * inv_l11 * inv_l22;

    float M00 = u00 * u00 * c.s00 + 2.0f * u00 * u01 * c.s01 + u01 * u01 * c.s11;
    float M01 = u11 * fmaf(u00, c.s01, u01 * c.s11);
    float M11 = u11 * u11 * c.s11;

    float sc = c.lamh * fv;
    cov.x = fmaf(sc, M00, F_EPS);
    cov.y = sc * M01;
    cov.z = sc * M01;
    cov.w = fmaf(sc, M11, F_EPS);
}

// ---------------------------------------------------------------------------
// Bulk-async + mbarrier helpers
// ---------------------------------------------------------------------------
__device__ __forceinline__ uint32_t s2u(const void* p) {
    return (uint32_t)__cvta_generic_to_shared(p);
}

__device__ __forceinline__ void mbar_init(uint32_t mb, uint32_t count) {
    asm volatile("mbarrier.init.shared.b64 [%0], %1;" :: "r"(mb), "r"(count) : "memory");
}

__device__ __forceinline__ void mbar_arrive(uint32_t mb) {
    asm volatile("mbarrier.arrive.release.cta.shared::cta.b64 _, [%0];" :: "r"(mb) : "memory");
}

__device__ __forceinline__ void mbar_wait(uint32_t mb, uint32_t phase) {
    uint32_t done;
    asm volatile(
        "{\n\t.reg .pred p;\n\t"
        "mbarrier.try_wait.parity.acquire.cta.shared::cta.b64 p, [%1], %2;\n\t"
        "selp.b32 %0, 1, 0, p;\n\t}"
        : "=r"(done) : "r"(mb), "r"(phase) : "memory");
    while (!done) {
        asm volatile(
            "{\n\t.reg .pred p;\n\t"
            "mbarrier.try_wait.parity.acquire.cta.shared::cta.b64 p, [%1], %2, 0x989680;\n\t"
            "selp.b32 %0, 1, 0, p;\n\t}"
            : "=r"(done) : "r"(mb), "r"(phase) : "memory");
    }
}

__device__ __forceinline__ void bulk_g2s(uint32_t smem_dst, const void* gmem_src,
                                         uint32_t bytes, uint32_t mb) {
    asm volatile(
        "cp.async.bulk.shared::cta.global.mbarrier::complete_tx::bytes [%0], [%1], %2, [%3];"
        :: "r"(smem_dst), "l"(gmem_src), "r"(bytes), "r"(mb) : "memory");
}

#define THREADS  256
#define NWARPS   (THREADS / 32)
#define CHUNK    512
#define STAGES   4          // 3 chunks in flight + 1 being consumed
#define MAX_CTAS (148 * 6)

__global__ void __launch_bounds__(THREADS)
poemv_kernel(const float* __restrict__ x, const float* __restrict__ p,
             const float* __restrict__ dlnf, const float* __restrict__ f,
             float* __restrict__ out_mean, float* __restrict__ out_cov, int B,
             const float* __restrict__ omega, const float* __restrict__ mu1,
             const float* __restrict__ mu2, const float* __restrict__ S1,
             const float* __restrict__ S2, const float* __restrict__ phi,
             const float* __restrict__ ct, const int* __restrict__ Lam,
             const int* __restrict__ rr) {
    // sbuf[stage][array][elem]; array: 0=x 1=p 2=d 3=f
    __shared__ alignas(16) float sbuf[STAGES][4][CHUNK];
    __shared__ alignas(8) unsigned long long s_full[STAGES];
    __shared__ alignas(8) unsigned long long s_empty[STAGES];

    const int tid = threadIdx.x;
    const int g = gridDim.x;
    const int nch = (B + CHUNK - 1) / CHUNK;

    if (tid == 0) {
        #pragma unroll
        for (int s = 0; s < STAGES; s++) {
            mbar_init(s2u(&s_full[s]), 1);        // producer tx-based
            mbar_init(s2u(&s_empty[s]), NWARPS);  // one arrive per warp
        }
        asm volatile("fence.proxy.async.shared::cta;" ::: "memory");
    }
    __syncthreads();

    // Prologue: issue up to STAGES-1 full chunks into slots 0..2.
    if (tid == 0) {
        #pragma unroll
        for (int st = 0; st < STAGES - 1; st++) {
            int k = blockIdx.x + st * g;
            int base = k * CHUNK;
            if (k < nch && base + CHUNK <= B) {
                uint32_t mb = s2u(&s_full[st]);
                asm volatile("mbarrier.arrive.expect_tx.shared.b64 _, [%0], %1;"
                             :: "r"(mb), "r"((uint32_t)(CHUNK * 16)) : "memory");
                bulk_g2s(s2u(&sbuf[st][0][0]), x + base,    CHUNK * 4, mb);
                bulk_g2s(s2u(&sbuf[st][1][0]), p + base,    CHUNK * 4, mb);
                bulk_g2s(s2u(&sbuf[st][2][0]), dlnf + base, CHUNK * 4, mb);
                bulk_g2s(s2u(&sbuf[st][3][0]), f + base,    CHUNK * 4, mb);
            }
        }
    }

    const Consts c = build_consts(omega, mu1, mu2, S1, S2, phi, ct, Lam, rr);

    uint32_t fph = 0;        // per-slot full-barrier parity (per thread)
    uint32_t eph = 0;        // per-slot empty-barrier parity (producer only)
    int it = 0;
    for (int k = blockIdx.x; k < nch; k += g, ++it) {
        const int slot = it & (STAGES - 1);

        // Producer (warp-0 thread 0 only): refill slot (it+3)&3 with chunk
        // k+3g, gated on that slot's consumption (empty barrier), NOT on a
        // CTA-wide sync. Other warps run free.
        if (tid == 0) {
            int kn = k + (STAGES - 1) * g;
            int nbase = kn * CHUNK;
            if (kn < nch && nbase + CHUNK <= B) {
                const int ns = (it + STAGES - 1) & (STAGES - 1);
                if (it >= 1) {   // slot was filled before; wait for consumption
                    mbar_wait(s2u(&s_empty[ns]), (eph >> ns) & 1u);
                    eph ^= 1u << ns;
                }
                uint32_t mb = s2u(&s_full[ns]);
                asm volatile("mbarrier.arrive.expect_tx.shared.b64 _, [%0], %1;"
                             :: "r"(mb), "r"((uint32_t)(CHUNK * 16)) : "memory");
                bulk_g2s(s2u(&sbuf[ns][0][0]), x + nbase,    CHUNK * 4, mb);
                bulk_g2s(s2u(&sbuf[ns][1][0]), p + nbase,    CHUNK * 4, mb);
                bulk_g2s(s2u(&sbuf[ns][2][0]), dlnf + nbase, CHUNK * 4, mb);
                bulk_g2s(s2u(&sbuf[ns][3][0]), f + nbase,    CHUNK * 4, mb);
            }
        }

        const int base = k * CHUNK;
        const bool full = (base + CHUNK <= B);

        if (full) {
            mbar_wait(s2u(&s_full[slot]), (fph >> slot) & 1u);
            fph ^= 1u << slot;

            const int s = tid * 2;
            const int i0 = base + s;
            float2 xv = *(const float2*)&sbuf[slot][0][s];
            float2 pv = *(const float2*)&sbuf[slot][1][s];
            float2 dv = *(const float2*)&sbuf[slot][2][s];
            float2 fv = *(const float2*)&sbuf[slot][3][s];

            float m0, m1, m2, m3;
            float4 c0, c1;
            compute_elem(c, xv.x, pv.x, dv.x, fv.x, m0, m1, c0);
            compute_elem(c, xv.y, pv.y, dv.y, fv.y, m2, m3, c1);

            *(float4*)(out_mean + (size_t)2 * i0) = make_float4(m0, m1, m2, m3);
            float4* cb = (float4*)(out_cov + (size_t)4 * i0);
            cb[0] = c0; cb[1] = c1;

            // Warp-level consumption signal (1 arrive per warp, count=8).
            __syncwarp();
            if ((tid & 31) == 0) mbar_arrive(s2u(&s_empty[slot]));
        } else {
            // partial tail chunk: direct guarded global loads, no slot used
            for (int kk = 0; kk < 2; kk++) {
                int i = base + tid * 2 + kk;
                if (i < B) {
                    float m0, m1; float4 cvv;
                    compute_elem(c, x[i], p[i], dlnf[i], f[i], m0, m1, cvv);
                    out_mean[(size_t)2 * i]     = m0;
                    out_mean[(size_t)2 * i + 1] = m1;
                    float* cb = out_cov + (size_t)4 * i;
                    cb[0] = cvv.x; cb[1] = cvv.y; cb[2] = cvv.z; cb[3] = cvv.w;
                }
            }
        }
    }
}

extern "C" void kernel_launch(void* const* d_in, const int* in_sizes, int n_in,
                              void* d_out, int out_size) {
    const float* x     = (const float*)d_in[0];
    const float* omega = (const float*)d_in[1];
    const float* p     = (const float*)d_in[2];
    const float* dlnf  = (const float*)d_in[3];
    const float* f     = (const float*)d_in[4];
    const float* mu1   = (const float*)d_in[5];
    const float* mu2   = (const float*)d_in[6];
    const float* S1    = (const float*)d_in[7];
    const float* S2    = (const float*)d_in[8];
    const float* phi   = (const float*)d_in[9];
    const float* ct    = (const float*)d_in[10];
    const int*   Lam   = (const int*)d_in[11];
    const int*   r     = (const int*)d_in[12];

    int B = in_sizes[0];
    float* out      = (float*)d_out;
    float* out_mean = out;                       // (B, 2) flattened
    float* out_cov  = out + (size_t)B * 2;       // (B, 2, 2) flattened

    int chunks = (B + CHUNK - 1) / CHUNK;
    int grid = chunks < MAX_CTAS ? chunks : MAX_CTAS;
    poemv_kernel<<<grid, THREADS>>>(x, p, dlnf, f, out_mean, out_cov, B,
                                    omega, mu1, mu2, S1, S2, phi, ct, Lam, r);
}